// round 10
// baseline (speedup 1.0000x reference)
#include <cuda_runtime.h>

#define INPUT_DIM 256
#define QN        12
#define NCTRL     25
#define NSPANS    22   // NCTRL - DEGREE

// ---------- f32x2 packed helpers (ptxas never auto-fuses; PTX only) ----------
__device__ __forceinline__ unsigned long long pack2(float a, float b) {
    unsigned long long r;
    asm("mov.b64 %0, {%1, %2};" : "=l"(r) : "f"(a), "f"(b));
    return r;
}
__device__ __forceinline__ void fma2(unsigned long long& d, unsigned long long a,
                                     unsigned long long b) {
    asm("fma.rn.f32x2 %0, %1, %2, %3;" : "=l"(d) : "l"(a), "l"(b), "l"(d));
}
__device__ __forceinline__ void unpack2(unsigned long long v, float& x, float& y) {
    asm("mov.b64 {%0, %1}, %2;" : "=f"(x), "=f"(y) : "l"(v));
}

// GEMM partials for the (Lo,Hi) role-swapped pair + vector reduce-scatter.
// Leaves u of value (lane&15) in UOUT: point A on lanes 0..15, B on 16..31.
#define GEMM_TWO(EL0, EL1, EH0, EH1, UOUT) do {                                \
    float rL[QN], rH[QN];                                                      \
    {                                                                          \
        const unsigned long long p0 = pack2((EL0).x, (EL0).y);                 \
        const unsigned long long p1 = pack2((EL0).z, (EL0).w);                 \
        const unsigned long long p2 = pack2((EL1).x, (EL1).y);                 \
        const unsigned long long p3 = pack2((EL1).z, (EL1).w);                 \
        _Pragma("unroll")                                                      \
        for (int q = 0; q < QN; q++) {                                         \
            unsigned long long acc = 0ull;                                     \
            fma2(acc, p0, wreg[q * 4 + 0]);                                    \
            fma2(acc, p1, wreg[q * 4 + 1]);                                    \
            fma2(acc, p2, wreg[q * 4 + 2]);                                    \
            fma2(acc, p3, wreg[q * 4 + 3]);                                    \
            float x, y; unpack2(acc, x, y);                                    \
            rL[q] = x + y;                                                     \
        }                                                                      \
    }                                                                          \
    {                                                                          \
        const unsigned long long p0 = pack2((EH0).x, (EH0).y);                 \
        const unsigned long long p1 = pack2((EH0).z, (EH0).w);                 \
        const unsigned long long p2 = pack2((EH1).x, (EH1).y);                 \
        const unsigned long long p3 = pack2((EH1).z, (EH1).w);                 \
        _Pragma("unroll")                                                      \
        for (int q = 0; q < QN; q++) {                                         \
            unsigned long long acc = 0ull;                                     \
            fma2(acc, p0, wreg[q * 4 + 0]);                                    \
            fma2(acc, p1, wreg[q * 4 + 1]);                                    \
            fma2(acc, p2, wreg[q * 4 + 2]);                                    \
            fma2(acc, p3, wreg[q * 4 + 3]);                                    \
            float x, y; unpack2(acc, x, y);                                    \
            rH[q] = x + y;                                                     \
        }                                                                      \
    }                                                                          \
    float r[QN];                                                               \
    _Pragma("unroll")                                                          \
    for (int q = 0; q < QN; q++)                                               \
        r[q] = rL[q] + __shfl_xor_sync(0xffffffffu, rH[q], 16);                \
    _Pragma("unroll")                                                          \
    for (int j = 0; j < 4; j++) {                                              \
        const float keep = b3 ? r[j + 8] : r[j];                               \
        const float send = b3 ? r[j] : r[j + 8];                               \
        r[j] = keep + __shfl_xor_sync(0xffffffffu, send, 8);                   \
    }                                                                          \
    _Pragma("unroll")                                                          \
    for (int j = 4; j < 8; j++)                                                \
        r[j] = r[j] + __shfl_xor_sync(0xffffffffu, r[j], 8);                   \
    _Pragma("unroll")                                                          \
    for (int j = 0; j < 4; j++) {                                              \
        const float keep = b2 ? r[j + 4] : r[j];                               \
        const float send = b2 ? r[j] : r[j + 4];                               \
        r[j] = keep + __shfl_xor_sync(0xffffffffu, send, 4);                   \
    }                                                                          \
    _Pragma("unroll")                                                          \
    for (int j = 0; j < 2; j++) {                                              \
        const float keep = b1 ? r[j + 2] : r[j];                               \
        const float send = b1 ? r[j] : r[j + 2];                               \
        r[j] = keep + __shfl_xor_sync(0xffffffffu, send, 2);                   \
    }                                                                          \
    {                                                                          \
        const float keep = b0 ? r[1] : r[0];                                   \
        const float send = b0 ? r[0] : r[1];                                   \
        UOUT = keep + __shfl_xor_sync(0xffffffffu, send, 1);                   \
    }                                                                          \
} while (0)

// Divide-free de Boor on u (coeffs pre-multiplied by a); per-point sum -> V.
#define SPLINE_SUM(UIN, V) do {                                                \
    (V) = 0.0f;                                                                \
    if (active) {                                                              \
        const float uu = (UIN) + my_bi;                                        \
        const float e  = __expf(sc2 * uu);                                     \
        const float s  = __fdividef(1.0f, 1.0f + e);                           \
        float s22 = s * (float)NSPANS;                                         \
        int sp = (int)s22;                                                     \
        sp = sp > (NSPANS - 1) ? (NSPANS - 1) : (sp < 0 ? 0 : sp);             \
        const float fj = (float)sp;                                            \
        const float L1  = s22 - fj;                                            \
        const float R1  = 1.0f - L1;                                           \
        const float L2  = s22 - fmaxf(fj - 1.0f, 0.0f);                        \
        const float R2  = fminf(fj + 2.0f, (float)NSPANS) - s22;               \
        const float L3  = s22 - fmaxf(fj - 2.0f, 0.0f);                        \
        const float R3  = fminf(fj + 3.0f, (float)NSPANS) - s22;               \
        const float THIRD = 0.33333333333333333f;                              \
        const float i2a = (sp == 0)  ? 1.0f : 0.5f;                            \
        const float i2b = (sp == 21) ? 1.0f : 0.5f;                            \
        const float i3a = (sp == 0)  ? 1.0f : ((sp == 1)  ? 0.5f : THIRD);     \
        const float i3b = (sp == 0 || sp == 21) ? 0.5f : THIRD;                \
        const float i3c = (sp == 20) ? 0.5f : ((sp == 21) ? 1.0f : THIRD);     \
        float N0 = R1, N1 = L1, N2, N3, t, sv;                                 \
        t = N0 * i2a;  N0 = R1 * t;       sv = L2 * t;                         \
        t = N1 * i2b;  N1 = sv + R2 * t;  N2 = L1 * t;                         \
        t = N0 * i3a;  N0 = R1 * t;       sv = L3 * t;                         \
        t = N1 * i3b;  N1 = sv + R2 * t;  sv = L2 * t;                         \
        t = N2 * i3c;  N2 = sv + R3 * t;  N3 = L1 * t;                         \
        (V) = N0 * crow[sp]     + N1 * crow[sp + 1]                            \
            + N2 * crow[sp + 2] + N3 * crow[sp + 3];                           \
    }                                                                          \
    _Pragma("unroll")                                                          \
    for (int off = 8; off; off >>= 1)                                          \
        (V) += __shfl_xor_sync(0xffffffffu, (V), off);                         \
} while (0)

__global__ __launch_bounds__(128, 3)
void ka_bspline_kernel(const float* __restrict__ emb,
                       const float* __restrict__ W,
                       const float* __restrict__ b_inner,
                       const float* __restrict__ inner_scale,
                       const float* __restrict__ coeffs,
                       const float* __restrict__ a_out,
                       const float* __restrict__ b_out,
                       float* __restrict__ out,
                       int npts)
{
    __shared__ float csh[QN * NCTRL];
    // fold the outer weight a[q] into the coefficients
    for (int k = threadIdx.x; k < QN * NCTRL; k += blockDim.x)
        csh[k] = coeffs[k] * a_out[k / NCTRL];
    __syncthreads();

    const int  lane = threadIdx.x & 31;
    const bool hi16 = (lane & 16) != 0;
    const bool b3 = (lane & 8) != 0;
    const bool b2 = (lane & 4) != 0;
    const bool b1 = (lane & 2) != 0;
    const bool b0 = (lane & 1) != 0;

    // W resident in registers, f32x2-packed over adjacent dims.
    unsigned long long wreg[QN * 4];
#pragma unroll
    for (int q = 0; q < QN; q++) {
        const int D0 = 4 * lane;
        const int D1 = 128 + 4 * lane;
        const float* wr = W + q * INPUT_DIM;
        wreg[q * 4 + 0] = pack2(wr[D0],     wr[D0 + 1]);
        wreg[q * 4 + 1] = pack2(wr[D0 + 2], wr[D0 + 3]);
        wreg[q * 4 + 2] = pack2(wr[D1],     wr[D1 + 1]);
        wreg[q * 4 + 3] = pack2(wr[D1 + 2], wr[D1 + 3]);
    }

    const int  q15    = lane & 15;
    const bool active = (q15 < QN);
    const int  qc     = active ? q15 : 0;
    const float my_bi = b_inner[qc];
    const float* __restrict__ crow = csh + qc * NCTRL;

    const float sc2 = -2.0f * inner_scale[0];
    const float bo  = b_out[0];

    const int  wpb    = blockDim.x >> 5;
    const long T      = (long)gridDim.x * wpb;
    const long stride = 2 * T;
    long n = (long)blockIdx.x * wpb + (threadIdx.x >> 5);

    const float4* __restrict__ emb4 = (const float4*)emb;
    const float4 z4 = {0.f, 0.f, 0.f, 0.f};

    float4 eL0 = z4, eL1 = z4, eH0 = z4, eH1 = z4;
    float  u_prev = 0.0f;
    long   pA = -1, pB = -1;

    // ---- prime: compute u for the first pair, no spline yet ----
    if (n < npts) {
        {
            const long nLo = hi16 ? n + T : n;
            const long nHi = hi16 ? n : n + T;
            if (nLo < npts) { const float4* p = emb4 + (size_t)nLo * 64 + lane; eL0 = p[0]; eL1 = p[32]; }
            if (nHi < npts) { const float4* p = emb4 + (size_t)nHi * 64 + lane; eH0 = p[0]; eH1 = p[32]; }
        }
        GEMM_TWO(eL0, eL1, eH0, eH1, u_prev);
        pA = n; pB = n + T;
        n += stride;
        // load current bufs for the next pair
        eL0 = z4; eL1 = z4; eH0 = z4; eH1 = z4;
        {
            const long nLo = hi16 ? n + T : n;
            const long nHi = hi16 ? n : n + T;
            if (nLo < npts) { const float4* p = emb4 + (size_t)nLo * 64 + lane; eL0 = p[0]; eL1 = p[32]; }
            if (nHi < npts) { const float4* p = emb4 + (size_t)nHi * 64 + lane; eH0 = p[0]; eH1 = p[32]; }
        }
    }

    // ---- steady state: one straight-line block; spline(prev) overlaps
    //      GEMM+reduce(cur) in the scheduler ----
    while (n < npts) {
        const long nn = n + stride;

        // prefetch next pair
        float4 fL0 = z4, fL1 = z4, fH0 = z4, fH1 = z4;
        {
            const long mLo = hi16 ? nn + T : nn;
            const long mHi = hi16 ? nn : nn + T;
            if (mLo < npts) { const float4* p = emb4 + (size_t)mLo * 64 + lane; fL0 = p[0]; fL1 = p[32]; }
            if (mHi < npts) { const float4* p = emb4 + (size_t)mHi * 64 + lane; fH0 = p[0]; fH1 = p[32]; }
        }

        float u_cur;
        GEMM_TWO(eL0, eL1, eH0, eH1, u_cur);

        float v;
        SPLINE_SUM(u_prev, v);                 // independent of u_cur
        if (lane == 0)               out[pA] = v + bo;
        if (lane == 16 && pB < npts) out[pB] = v + bo;

        u_prev = u_cur;
        pA = n; pB = n + T;
        eL0 = fL0; eL1 = fL1; eH0 = fH0; eH1 = fH1;
        n = nn;
    }

    // ---- drain: spline + store for the last pair ----
    if (pA >= 0) {
        float v;
        SPLINE_SUM(u_prev, v);
        if (lane == 0)               out[pA] = v + bo;
        if (lane == 16 && pB < npts) out[pB] = v + bo;
    }
}

extern "C" void kernel_launch(void* const* d_in, const int* in_sizes, int n_in,
                              void* d_out, int out_size)
{
    const float* emb         = (const float*)d_in[0];
    const float* W           = (const float*)d_in[1];
    const float* b_inner     = (const float*)d_in[2];
    const float* inner_scale = (const float*)d_in[3];
    const float* coeffs      = (const float*)d_in[4];
    const float* a_out       = (const float*)d_in[5];
    const float* b_out       = (const float*)d_in[6];
    float* out = (float*)d_out;

    const int npts = in_sizes[0] / INPUT_DIM;

    ka_bspline_kernel<<<456, 128>>>(emb, W, b_inner, inner_scale, coeffs,
                                    a_out, b_out, out, npts);
}